// round 17
// baseline (speedup 1.0000x reference)
#include <cuda_runtime.h>
#include <cuda_fp16.h>
#include <cstdint>

#define NN 16384
#define DD 128
#define KG 64
#define BM 64
#define BN 64
#define NTILES (NN / BN)

// ---------------- scratch ----------------
__device__ __align__(16) float  g_g  [NN*KG];
__device__               float  g_sq [NN];
__device__ __align__(16) __half g_ghi[NN*KG];
__device__ __align__(16) __half g_hhi[(size_t)NN*DD];
__device__ __align__(16) float  g_x1 [NN*DD];
__device__ __align__(16) float  g_x2 [NN*DD];

// ---------------- helpers ----------------
__device__ __forceinline__ uint32_t smem_u32(const void* p) {
    uint32_t a;
    asm("{ .reg .u64 t; cvta.to.shared.u64 t, %1; cvt.u32.u64 %0, t; }" : "=r"(a) : "l"(p));
    return a;
}
__device__ __forceinline__ void cp16(uint32_t dst, const void* src) {
    asm volatile("cp.async.cg.shared.global [%0], [%1], 16;"
                 :: "r"(dst), "l"(__cvta_generic_to_global(src)) : "memory");
}
#define CP_COMMIT() asm volatile("cp.async.commit_group;" ::: "memory")
#define CP_WAIT1()  asm volatile("cp.async.wait_group 1;" ::: "memory")
#define CP_WAIT0()  asm volatile("cp.async.wait_group 0;" ::: "memory")

__device__ __forceinline__ void ldmx4(uint32_t* r, uint32_t addr) {
    asm volatile("ldmatrix.sync.aligned.m8n8.x4.shared.b16 {%0,%1,%2,%3}, [%4];"
                 : "=r"(r[0]), "=r"(r[1]), "=r"(r[2]), "=r"(r[3]) : "r"(addr));
}
__device__ __forceinline__ void ldmx4t(uint32_t* r, uint32_t addr) {
    asm volatile("ldmatrix.sync.aligned.m8n8.x4.trans.shared.b16 {%0,%1,%2,%3}, [%4];"
                 : "=r"(r[0]), "=r"(r[1]), "=r"(r[2]), "=r"(r[3]) : "r"(addr));
}
__device__ __forceinline__ void mma16816(float* d, const uint32_t* a, const uint32_t* b) {
    asm volatile("mma.sync.aligned.m16n8k16.row.col.f32.f16.f16.f32 "
                 "{%0,%1,%2,%3}, {%4,%5,%6,%7}, {%8,%9}, {%0,%1,%2,%3};"
                 : "+f"(d[0]), "+f"(d[1]), "+f"(d[2]), "+f"(d[3])
                 : "r"(a[0]), "r"(a[1]), "r"(a[2]), "r"(a[3]), "r"(b[0]), "r"(b[1]));
}
__device__ __forceinline__ uint32_t packh2(float x, float y) {
    __half2 r = __floats2half2_rn(x, y);
    return *reinterpret_cast<uint32_t*>(&r);
}
__device__ __forceinline__ float tanh_ap(float x) {
    float r;
    asm("tanh.approx.f32 %0, %1;" : "=f"(r) : "f"(x));
    return r;
}

// ---------------- g = relu(x @ gl_w + gl_b) ----------------
__global__ __launch_bounds__(256)
void proj_gl_kernel(const float* __restrict__ x, const float* __restrict__ W,
                    const float* __restrict__ b, float* __restrict__ out)
{
    __shared__ float sX[64 * DD];
    const int tid = threadIdx.x;
    const long row0 = (long)blockIdx.x * 64;
    #pragma unroll 4
    for (int i = tid; i < 64 * DD; i += 256) sX[i] = x[row0 * DD + i];
    __syncthreads();
    const int c = tid % 64, rg = tid / 64;
    float acc[16];
    #pragma unroll
    for (int i = 0; i < 16; i++) acc[i] = 0.f;
    #pragma unroll 4
    for (int k = 0; k < DD; k++) {
        const float wv = W[k * 64 + c];
        #pragma unroll
        for (int rr = 0; rr < 16; rr++)
            acc[rr] = fmaf(sX[(rg * 16 + rr) * DD + k], wv, acc[rr]);
    }
    const float bv = b[c];
    #pragma unroll
    for (int rr = 0; rr < 16; rr++)
        out[(row0 + rg * 16 + rr) * 64 + c] = fmaxf(acc[rr] + bv, 0.f);
}

// ---------------- sq + fp16 convert of g ----------------
__global__ __launch_bounds__(256)
void sqcvt_kernel(const float* __restrict__ g, float* __restrict__ sq,
                  __half* __restrict__ ghi)
{
    const int warp = (blockIdx.x * blockDim.x + threadIdx.x) >> 5;
    const int lane = threadIdx.x & 31;
    float a = g[(size_t)warp * KG + lane];
    float c = g[(size_t)warp * KG + 32 + lane];
    float s = a * a + c * c;
    #pragma unroll
    for (int off = 16; off; off >>= 1) s += __shfl_xor_sync(~0u, s, off);
    if (lane == 0) sq[warp] = s;
    ghi[(size_t)warp * KG + lane]      = __float2half_rn(a);
    ghi[(size_t)warp * KG + 32 + lane] = __float2half_rn(c);
}

// ---------------- h = x @ gnn_w + b, fp16 ----------------
__global__ __launch_bounds__(256)
void proj_gnn_kernel(const float* __restrict__ x, const float* __restrict__ W,
                     const float* __restrict__ b, __half* __restrict__ hhi)
{
    __shared__ float sX[64 * DD];
    const int tid = threadIdx.x;
    const long row0 = (long)blockIdx.x * 64;
    #pragma unroll 4
    for (int i = tid; i < 64 * DD; i += 256) sX[i] = x[row0 * DD + i];
    __syncthreads();
    const int c = tid % 128, rg = tid / 128;
    float acc[32];
    #pragma unroll
    for (int i = 0; i < 32; i++) acc[i] = 0.f;
    #pragma unroll 4
    for (int k = 0; k < DD; k++) {
        const float wv = W[k * 128 + c];
        #pragma unroll
        for (int rr = 0; rr < 32; rr++)
            acc[rr] = fmaf(sX[(rg * 32 + rr) * DD + k], wv, acc[rr]);
    }
    const float bv = b[c];
    #pragma unroll
    for (int rr = 0; rr < 32; rr++)
        hhi[(size_t)(row0 + rg * 32 + rr) * DD + c] = __float2half_rn(acc[rr] + bv);
}

// ---------------- fused flash layer: 128-thread CTAs, 2 per SM ----------------
// Per-warp structure identical to the validated 950us kernel; only the CTA
// partitioning changes (independent barrier domains -> cross-CTA phase overlap).
#define QH_OFF 0u
#define KH_OFF 9216u         // + buf*9216
#define VH_OFF 27648u        // + buf*17408
#define SQ_OFF 62464u        // + buf*256
#define SM_TOTAL 62976u
#define KROW 144u
#define VROW 272u

__global__ __launch_bounds__(128, 2)
void flash_kernel(const __half* __restrict__ ghi, const __half* __restrict__ hhi,
                  const float* __restrict__ sq, float* __restrict__ outp,
                  const float* __restrict__ tempp, const float* __restrict__ thetap, int do_relu)
{
    extern __shared__ char smem[];
    const uint32_t sb = smem_u32(smem);
    const int tid = threadIdx.x, wid = tid >> 5, lane = tid & 31;
    const int row0 = blockIdx.x * BM;
    const int g = lane >> 2, tq = lane & 3;
    const int mb = wid * 16;

    const float t  = 1.0f + *tempp;
    const float th = 5.0f + *thetap;
    const float tH = 0.5f * t;
    // sigmoid(z) = 0.5*tanh(z/2) + 0.5 ; z/2 = t*S + 0.5*(th - t*sq_i) - 0.5*t*sq_j
    const float bi0h = 0.5f * (th - t * sq[row0 + mb + g]);
    const float bi1h = 0.5f * (th - t * sq[row0 + mb + 8 + g]);

    // ---- prologue: Q tile (group 0): 64 rows x 8 chunks = 512 ops ----
    #pragma unroll
    for (int i = tid; i < 512; i += 128) {
        int row = i >> 3, ch = i & 7;
        cp16(sb + QH_OFF + row * KROW + ch * 16, ghi + (size_t)(row0 + row) * KG + ch * 8);
    }
    CP_COMMIT();

    // ---- tile 0 (group 1): K 512 + V 1024 + SQ 16 = 1552 ops ----
    #pragma unroll 1
    for (int i = tid; i < 1552; i += 128) {
        if (i < 512) {
            int row = i >> 3, ch = i & 7;
            cp16(sb + KH_OFF + row * KROW + ch * 16, ghi + (size_t)row * KG + ch * 8);
        } else if (i < 1536) {
            int c = i - 512, row = c >> 4, ch = c & 15;
            cp16(sb + VH_OFF + row * VROW + ch * 16, hhi + (size_t)row * DD + ch * 8);
        } else {
            int c = i - 1536;                       // 0..15 -> full 64 floats of sq_j
            cp16(sb + SQ_OFF + c * 16, sq + c * 4);
        }
    }
    CP_COMMIT();

    float o[16][4];
    #pragma unroll
    for (int i = 0; i < 16; i++) { o[i][0] = o[i][1] = o[i][2] = o[i][3] = 0.f; }
    float rs0 = 0.f, rs1 = 0.f;

    const uint32_t q_off  = (uint32_t)(mb + (lane & 15)) * KROW + ((lane & 16) ? 16u : 0u);
    const uint32_t k_off4 = (uint32_t)(lane & 7) * KROW + (uint32_t)(lane >> 3) * 16u;
    const uint32_t v_off4 = (uint32_t)(lane & 15) * VROW + ((lane & 16) ? 16u : 0u);

    // Q fragments: persistent across the whole j-loop
    CP_WAIT1();
    __syncthreads();
    uint32_t ah[4][4];
    #pragma unroll
    for (int ks = 0; ks < 4; ks++)
        ldmx4(ah[ks], sb + QH_OFF + q_off + ks * 32);

    for (int tt = 0; tt < NTILES; tt++) {
        const int buf = tt & 1;
        if (tt + 1 < NTILES) {
            const int j0 = (tt + 1) * BN, nb = buf ^ 1;
            #pragma unroll 1
            for (int i = tid; i < 1552; i += 128) {
                if (i < 512) {
                    int row = i >> 3, ch = i & 7;
                    cp16(sb + KH_OFF + nb * 9216u + row * KROW + ch * 16,
                         ghi + (size_t)(j0 + row) * KG + ch * 8);
                } else if (i < 1536) {
                    int c = i - 512, row = c >> 4, ch = c & 15;
                    cp16(sb + VH_OFF + nb * 17408u + row * VROW + ch * 16,
                         hhi + (size_t)(j0 + row) * DD + ch * 8);
                } else {
                    int c = i - 1536;               // full 64 floats
                    cp16(sb + SQ_OFF + nb * 256u + c * 16, sq + j0 + c * 4);
                }
            }
            CP_COMMIT();
            CP_WAIT1();
        } else {
            CP_WAIT0();
        }
        __syncthreads();

        const uint32_t khb = sb + KH_OFF + buf * 9216u;
        const uint32_t vhb = sb + VH_OFF + buf * 17408u;
        const float* sqj = (const float*)(smem + SQ_OFF + buf * 256u);

        // ---- GEMM1: S = Qh.Kh ----
        float S[8][4];
        #pragma unroll
        for (int nt = 0; nt < 8; nt++) {
            float d[4] = {0.f, 0.f, 0.f, 0.f};
            #pragma unroll
            for (int kp = 0; kp < 2; kp++) {
                uint32_t bh[4];
                ldmx4(bh, khb + (uint32_t)nt * 8 * KROW + k_off4 + kp * 64);
                mma16816(d, ah[2*kp],     bh);
                mma16816(d, ah[2*kp + 1], bh + 2);
            }
            S[nt][0] = d[0]; S[nt][1] = d[1]; S[nt][2] = d[2]; S[nt][3] = d[3];
        }

        // ---- sigmoid via fp32 tanh.approx -> W fragments + rowsum ----
        uint32_t whi[4][4];
        #pragma unroll
        for (int nt = 0; nt < 8; nt++) {
            float q0 = sqj[nt * 8 + tq * 2], q1 = sqj[nt * 8 + tq * 2 + 1];
            float c0 = bi0h - tH * q0, c1 = bi0h - tH * q1;
            float c2 = bi1h - tH * q0, c3 = bi1h - tH * q1;
            float w0 = fmaf(0.5f, tanh_ap(fmaf(t, S[nt][0], c0)), 0.5f);
            float w1 = fmaf(0.5f, tanh_ap(fmaf(t, S[nt][1], c1)), 0.5f);
            float w2 = fmaf(0.5f, tanh_ap(fmaf(t, S[nt][2], c2)), 0.5f);
            float w3 = fmaf(0.5f, tanh_ap(fmaf(t, S[nt][3], c3)), 0.5f);
            rs0 += w0 + w1;  rs1 += w2 + w3;
            const int kj = nt >> 1;
            if ((nt & 1) == 0) { whi[kj][0] = packh2(w0, w1); whi[kj][1] = packh2(w2, w3); }
            else               { whi[kj][2] = packh2(w0, w1); whi[kj][3] = packh2(w2, w3); }
        }

        // ---- GEMM2: O += Wh.Vh ----
        #pragma unroll
        for (int ctp = 0; ctp < 8; ctp++) {
            const uint32_t cb = (uint32_t)ctp * 32;
            #pragma unroll
            for (int ks = 0; ks < 4; ks++) {
                uint32_t bh[4];
                ldmx4t(bh, vhb + (uint32_t)ks * 16 * VROW + v_off4 + cb);
                mma16816(o[2*ctp],     whi[ks], bh);
                mma16816(o[2*ctp + 1], whi[ks], bh + 2);
            }
        }
        __syncthreads();
    }

    // ---- epilogue ----
    rs0 += __shfl_xor_sync(~0u, rs0, 1); rs0 += __shfl_xor_sync(~0u, rs0, 2);
    rs1 += __shfl_xor_sync(~0u, rs1, 1); rs1 += __shfl_xor_sync(~0u, rs1, 2);
    const float inv0 = __fdividef(1.f, rs0);
    const float inv1 = __fdividef(1.f, rs1);
    const size_t r0 = (size_t)(row0 + mb + g) * DD + tq * 2;
    const size_t r1 = r0 + 8 * DD;
    #pragma unroll
    for (int ct = 0; ct < 16; ct++) {
        float2 v0 = make_float2(o[ct][0] * inv0, o[ct][1] * inv0);
        float2 v1 = make_float2(o[ct][2] * inv1, o[ct][3] * inv1);
        if (do_relu) {
            v0.x = fmaxf(v0.x, 0.f); v0.y = fmaxf(v0.y, 0.f);
            v1.x = fmaxf(v1.x, 0.f); v1.y = fmaxf(v1.y, 0.f);
        }
        *(float2*)(outp + r0 + ct * 8) = v0;
        *(float2*)(outp + r1 + ct * 8) = v1;
    }
}

// ---------------- head: softmax(x @ out_w + out_b) ----------------
__global__ __launch_bounds__(256)
void out_kernel(const float* __restrict__ x, const float* __restrict__ W,
                const float* __restrict__ b, float* __restrict__ out)
{
    const int row  = (blockIdx.x * blockDim.x + threadIdx.x) >> 5;
    const int lane = threadIdx.x & 31;
    if (row >= NN) return;
    const float* xr = x + (size_t)row * DD;
    float acc = 0.f;
    if (lane < 10) {
        #pragma unroll 8
        for (int k = 0; k < DD; k++) acc = fmaf(xr[k], W[k * 10 + lane], acc);
        acc += b[lane];
    }
    float m = (lane < 10) ? acc : -3.402823466e38f;
    #pragma unroll
    for (int off = 16; off; off >>= 1) m = fmaxf(m, __shfl_xor_sync(~0u, m, off));
    float e = (lane < 10) ? __expf(acc - m) : 0.f;
    float s = e;
    #pragma unroll
    for (int off = 16; off; off >>= 1) s += __shfl_xor_sync(~0u, s, off);
    if (lane < 10) out[(size_t)row * 10 + lane] = e / s;
}

extern "C" void kernel_launch(void* const* d_in, const int* in_sizes, int n_in,
                              void* d_out, int out_size)
{
    const float* feat   = (const float*)d_in[0];
    const float* gl_w0  = (const float*)d_in[1];
    const float* gl_b0  = (const float*)d_in[2];
    const float* gl_w1  = (const float*)d_in[3];
    const float* gl_b1  = (const float*)d_in[4];
    const float* gnn_w0 = (const float*)d_in[5];
    const float* gnn_b0 = (const float*)d_in[6];
    const float* gnn_w1 = (const float*)d_in[7];
    const float* gnn_b1 = (const float*)d_in[8];
    const float* out_w  = (const float*)d_in[9];
    const float* out_b  = (const float*)d_in[10];
    const float* temp   = (const float*)d_in[11];
    const float* theta  = (const float*)d_in[12];
    float* out = (float*)d_out;

    float *pg, *psq, *px1, *px2;
    __half *pghi, *phhi;
    cudaGetSymbolAddress((void**)&pg,   g_g);
    cudaGetSymbolAddress((void**)&psq,  g_sq);
    cudaGetSymbolAddress((void**)&pghi, g_ghi);
    cudaGetSymbolAddress((void**)&phhi, g_hhi);
    cudaGetSymbolAddress((void**)&px1,  g_x1);
    cudaGetSymbolAddress((void**)&px2,  g_x2);

    cudaFuncSetAttribute(flash_kernel, cudaFuncAttributeMaxDynamicSharedMemorySize, SM_TOTAL);

    proj_gl_kernel <<<NN / 64, 256>>>(feat, gl_w0, gl_b0, pg);
    sqcvt_kernel   <<<NN / 8,  256>>>(pg, psq, pghi);
    proj_gnn_kernel<<<NN / 64, 256>>>(feat, gnn_w0, gnn_b0, phhi);
    flash_kernel   <<<NN / BM, 128, SM_TOTAL>>>(pghi, phhi, psq, px1, temp, theta, 1);

    proj_gl_kernel <<<NN / 64, 256>>>(px1, gl_w1, gl_b1, pg);
    sqcvt_kernel   <<<NN / 8,  256>>>(pg, psq, pghi);
    proj_gnn_kernel<<<NN / 64, 256>>>(px1, gnn_w1, gnn_b1, phhi);
    flash_kernel   <<<NN / BM, 128, SM_TOTAL>>>(pghi, phhi, psq, px2, temp, theta, 0);

    out_kernel<<<NN / 8, 256>>>(px2, out_w, out_b, out);
}